// round 1
// baseline (speedup 1.0000x reference)
#include <cuda_runtime.h>
#include <math.h>

#define BATCH 256

// ------------------- scratch (alloc-free rule: device globals) -------------------
__device__ float g_a[BATCH * 32 * 64 * 64];   // conv1 out / deconv1 out   (134 MB)
__device__ float g_b[BATCH * 64 * 32 * 32];   // conv2 out                 (67 MB)
__device__ float g_c[BATCH * 64 * 32 * 32];   // conv3 out / dec1 out      (67 MB)
__device__ float g_z[BATCH * 32 * 32 * 32];   // encoder latent z          (33.5 MB)
__device__ float g_q[BATCH * 32 * 32 * 32];   // quantized latent          (33.5 MB)
__device__ float g_lpart[1024];               // per-block loss partials

// ------------------- generic direct conv (thread per output) -------------------
// Block: 256 threads over spatial positions; grid = (HOUT*HOUT/256, COUT, BATCH).
// Weights for this block's single output channel cached in shared.
template<int CIN, int HIN, int K, int S, int P, bool RELU>
__global__ void k_conv(const float* __restrict__ in, const float* __restrict__ w,
                       const float* __restrict__ bias, float* __restrict__ out) {
    constexpr int HOUT = (HIN + 2 * P - K) / S + 1;
    __shared__ float sw[CIN * K * K];
    const int co = blockIdx.y;
    const int n  = blockIdx.z;
    const int t  = threadIdx.x;
    const int COUT = gridDim.y;
    for (int i = t; i < CIN * K * K; i += 256) sw[i] = w[co * CIN * K * K + i];
    __syncthreads();

    const int p  = blockIdx.x * 256 + t;
    const int oy = p / HOUT;
    const int ox = p % HOUT;
    float acc = bias[co];
    const float* ib = in + (long)n * CIN * HIN * HIN;
    const int iy0 = oy * S - P, ix0 = ox * S - P;

    for (int ci = 0; ci < CIN; ci++) {
        const float* ic = ib + ci * HIN * HIN;
        const float* wc = sw + ci * K * K;
        #pragma unroll
        for (int ky = 0; ky < K; ky++) {
            int iy = iy0 + ky;
            if ((unsigned)iy < (unsigned)HIN) {
                const float* row = ic + iy * HIN;
                #pragma unroll
                for (int kx = 0; kx < K; kx++) {
                    int ix = ix0 + kx;
                    if ((unsigned)ix < (unsigned)HIN)
                        acc = fmaf(row[ix], wc[ky * K + kx], acc);
                }
            }
        }
    }
    float r = RELU ? fmaxf(acc, 0.f) : acc;
    out[(((long)n * COUT + co) * HOUT + oy) * HOUT + ox] = r;
}

// ------------------- transposed conv k=4 s=2 p=1 (torch semantics) -------------------
// w layout: [CIN, COUT, 4, 4]. out[oy,ox] pulls from iy=(oy+1-ky)/2 for ky with
// matching parity -> exactly 2x2 taps per output.
template<int CIN, int HIN, bool RELU, bool SIG>
__global__ void k_deconv(const float* __restrict__ in, const float* __restrict__ w,
                         const float* __restrict__ bias, float* __restrict__ out) {
    constexpr int HOUT = HIN * 2;
    __shared__ float sw[CIN * 16];
    const int co = blockIdx.y;
    const int n  = blockIdx.z;
    const int t  = threadIdx.x;
    const int COUT = gridDim.y;
    for (int i = t; i < CIN * 16; i += 256) {
        int ci = i >> 4, kk = i & 15;
        sw[i] = w[(ci * COUT + co) * 16 + kk];
    }
    __syncthreads();

    const int p  = blockIdx.x * 256 + t;
    const int oy = p / HOUT;
    const int ox = p % HOUT;
    const int ky0 = (oy + 1) & 1;
    const int kx0 = (ox + 1) & 1;
    const int iyA = (oy + 1 - ky0) >> 1, iyB = iyA - 1;
    const int ixA = (ox + 1 - kx0) >> 1, ixB = ixA - 1;
    const bool vyA = (unsigned)iyA < (unsigned)HIN, vyB = (unsigned)iyB < (unsigned)HIN;
    const bool vxA = (unsigned)ixA < (unsigned)HIN, vxB = (unsigned)ixB < (unsigned)HIN;

    float acc = bias[co];
    const float* ib = in + (long)n * CIN * HIN * HIN;
    for (int ci = 0; ci < CIN; ci++) {
        const float* ic = ib + ci * HIN * HIN;
        const float* wc = sw + ci * 16;
        if (vyA) {
            const float* r = ic + iyA * HIN;
            if (vxA) acc = fmaf(r[ixA], wc[ky0 * 4 + kx0],     acc);
            if (vxB) acc = fmaf(r[ixB], wc[ky0 * 4 + kx0 + 2], acc);
        }
        if (vyB) {
            const float* r = ic + iyB * HIN;
            if (vxA) acc = fmaf(r[ixA], wc[(ky0 + 2) * 4 + kx0],     acc);
            if (vxB) acc = fmaf(r[ixB], wc[(ky0 + 2) * 4 + kx0 + 2], acc);
        }
    }
    float v = acc;
    if (RELU) v = fmaxf(v, 0.f);
    if (SIG)  v = 1.f / (1.f + expf(-v));
    out[(((long)n * COUT + co) * HOUT + oy) * HOUT + ox] = v;
}

// ------------------- vector quantization -------------------
// One thread per latent position. Codebook streamed through shared in
// 4 chunks of 128 codewords (16 KB + norms). dist = ||c||^2 - 2 z.c
// (same argmin as reference up to the constant ||z||^2 shift).
// Strict < preserves jnp.argmin first-occurrence tie semantics.
__global__ void k_vq(const float* __restrict__ z, const float* __restrict__ cb,
                     float* __restrict__ q, float* __restrict__ lpart) {
    __shared__ float scb[128 * 32];
    __shared__ float scn[128];
    __shared__ float red[256];
    const int t   = threadIdx.x;
    const int pos = blockIdx.x * 256 + t;      // 0 .. 262143
    const int n   = pos >> 10;
    const int p   = pos & 1023;

    const float* zp = z + (long)n * 32 * 1024 + p;
    float zv[32];
    #pragma unroll
    for (int d = 0; d < 32; d++) zv[d] = zp[d * 1024];

    float best = 3.4e38f;
    int   bi   = 0;
    for (int ch = 0; ch < 4; ch++) {
        __syncthreads();
        for (int i = t; i < 4096; i += 256) scb[i] = cb[ch * 4096 + i];
        __syncthreads();
        if (t < 128) {
            float s = 0.f;
            const float* c = scb + t * 32;
            #pragma unroll
            for (int d = 0; d < 32; d++) s = fmaf(c[d], c[d], s);
            scn[t] = s;
        }
        __syncthreads();
        for (int k = 0; k < 128; k++) {
            const float* c = scb + k * 32;
            float dot = 0.f;
            #pragma unroll
            for (int d = 0; d < 32; d++) dot = fmaf(zv[d], c[d], dot);
            float dist = fmaf(-2.f, dot, scn[k]);
            if (dist < best) { best = dist; bi = ch * 128 + k; }
        }
    }

    // quantize + local loss
    float lsum = 0.f;
    const float* c = cb + bi * 32;
    float* qp = q + (long)n * 32 * 1024 + p;
    #pragma unroll
    for (int d = 0; d < 32; d++) {
        float qv = __ldg(c + d);
        qp[d * 1024] = qv;
        float df = qv - zv[d];
        lsum = fmaf(df, df, lsum);
    }

    red[t] = lsum;
    __syncthreads();
    for (int s = 128; s > 0; s >>= 1) {
        if (t < s) red[t] += red[t + s];
        __syncthreads();
    }
    if (t == 0) lpart[blockIdx.x] = red[0];
}

// deterministic fixed-order final reduction: vq_loss = 1.26 * mean
__global__ void k_loss(const float* __restrict__ lpart, float* __restrict__ out,
                       int out_size) {
    __shared__ float red[256];
    const int t = threadIdx.x;
    red[t] = lpart[t] + lpart[t + 256] + lpart[t + 512] + lpart[t + 768];
    __syncthreads();
    for (int s = 128; s > 0; s >>= 1) {
        if (t < s) red[t] += red[t + s];
        __syncthreads();
    }
    if (t == 0) out[out_size - 1] = 1.26f * red[0] / 8388608.0f;
}

// ------------------- launch -------------------
extern "C" void kernel_launch(void* const* d_in, const int* in_sizes, int n_in,
                              void* d_out, int out_size) {
    const float* x   = (const float*)d_in[0];
    const float* ew1 = (const float*)d_in[1];  const float* eb1 = (const float*)d_in[2];
    const float* ew2 = (const float*)d_in[3];  const float* eb2 = (const float*)d_in[4];
    const float* ew3 = (const float*)d_in[5];  const float* eb3 = (const float*)d_in[6];
    const float* ew4 = (const float*)d_in[7];  const float* eb4 = (const float*)d_in[8];
    const float* cb  = (const float*)d_in[9];
    const float* dw1 = (const float*)d_in[10]; const float* db1 = (const float*)d_in[11];
    const float* tw1 = (const float*)d_in[12]; const float* tb1 = (const float*)d_in[13];
    const float* tw2 = (const float*)d_in[14]; const float* tb2 = (const float*)d_in[15];
    float* out = (float*)d_out;

    float *pa, *pb, *pc, *pz, *pq, *pl;
    cudaGetSymbolAddress((void**)&pa, g_a);
    cudaGetSymbolAddress((void**)&pb, g_b);
    cudaGetSymbolAddress((void**)&pc, g_c);
    cudaGetSymbolAddress((void**)&pz, g_z);
    cudaGetSymbolAddress((void**)&pq, g_q);
    cudaGetSymbolAddress((void**)&pl, g_lpart);

    // Encoder
    k_conv<1, 128, 4, 2, 1, true ><<<dim3(16, 32, BATCH), 256>>>(x,  ew1, eb1, pa); // ->[256,32,64,64]
    k_conv<32, 64, 4, 2, 1, true ><<<dim3( 4, 64, BATCH), 256>>>(pa, ew2, eb2, pb); // ->[256,64,32,32]
    k_conv<64, 32, 3, 1, 1, true ><<<dim3( 4, 64, BATCH), 256>>>(pb, ew3, eb3, pc); // ->[256,64,32,32]
    k_conv<64, 32, 1, 1, 0, false><<<dim3( 4, 32, BATCH), 256>>>(pc, ew4, eb4, pz); // ->[256,32,32,32]

    // Vector quantization (+ per-block loss partials)
    k_vq<<<1024, 256>>>(pz, cb, pq, pl);

    // Decoder
    k_conv<32, 32, 3, 1, 1, true ><<<dim3( 4, 64, BATCH), 256>>>(pq, dw1, db1, pc); // ->[256,64,32,32]
    k_deconv<64, 32, true,  false><<<dim3(16, 32, BATCH), 256>>>(pc, tw1, tb1, pa); // ->[256,32,64,64]
    k_deconv<32, 64, false, true ><<<dim3(64,  1, BATCH), 256>>>(pa, tw2, tb2, out);// ->[256,1,128,128]

    // Deterministic loss finalize into out[out_size-1]
    k_loss<<<1, 256>>>(pl, out, out_size);
}

// round 2
// speedup vs baseline: 4.0973x; 4.0973x over previous
#include <cuda_runtime.h>
#include <math.h>

#define BATCH 256

// ------------------- scratch (alloc-free rule: device globals) -------------------
__device__ float g_a[BATCH * 32 * 64 * 64];   // conv1 out / deconv1 out
__device__ float g_b[BATCH * 64 * 32 * 32];   // conv2 out
__device__ float g_c[BATCH * 64 * 32 * 32];   // conv3 out / dec1 out
__device__ float g_z[BATCH * 32 * 32 * 32];   // encoder latent z
__device__ float g_q[BATCH * 32 * 32 * 32];   // quantized latent
__device__ float g_lpart[512];                // per-block loss partials

// ------------------- register-tiled direct conv -------------------
// Each thread computes CT output channels x ST consecutive-x spatial positions.
// Per (ci,ky,kx): ST input loads + CT smem weight reads -> CT*ST FMAs.
// grid = (HOUT*HOUT/(256*ST), COUT/CT, BATCH), block = 256.
template<int CIN, int HIN, int K, int S, int P, int COUT, int CT, int ST, bool RELU>
__global__ void k_convt(const float* __restrict__ in, const float* __restrict__ w,
                        const float* __restrict__ bias, float* __restrict__ out) {
    constexpr int HOUT = (HIN + 2 * P - K) / S + 1;
    constexpr int KK = K * K;
    __shared__ float sw[CT * CIN * KK];
    const int co0 = blockIdx.y * CT;
    const int n   = blockIdx.z;
    const int t   = threadIdx.x;
    for (int i = t; i < CT * CIN * KK; i += 256) {
        int c = i / (CIN * KK), rest = i % (CIN * KK);
        sw[i] = w[(co0 + c) * CIN * KK + rest];
    }
    __syncthreads();

    const int p0  = (blockIdx.x * 256 + t) * ST;
    const int oy  = p0 / HOUT;
    const int ox0 = p0 % HOUT;          // multiple of ST (ST divides HOUT)

    float acc[CT][ST];
    #pragma unroll
    for (int c = 0; c < CT; c++) {
        float bv = bias[co0 + c];
        #pragma unroll
        for (int s = 0; s < ST; s++) acc[c][s] = bv;
    }

    const float* ib = in + (long)n * CIN * HIN * HIN;
    for (int ci = 0; ci < CIN; ci++) {
        const float* ic = ib + ci * HIN * HIN;
        #pragma unroll
        for (int ky = 0; ky < K; ky++) {
            int iy = oy * S - P + ky;
            if ((unsigned)iy < (unsigned)HIN) {
                const float* row = ic + iy * HIN;
                #pragma unroll
                for (int kx = 0; kx < K; kx++) {
                    float xv[ST];
                    #pragma unroll
                    for (int s = 0; s < ST; s++) {
                        int ix = (ox0 + s) * S - P + kx;
                        xv[s] = ((unsigned)ix < (unsigned)HIN) ? row[ix] : 0.f;
                    }
                    #pragma unroll
                    for (int c = 0; c < CT; c++) {
                        float wv = sw[(c * CIN + ci) * KK + ky * K + kx];
                        #pragma unroll
                        for (int s = 0; s < ST; s++)
                            acc[c][s] = fmaf(xv[s], wv, acc[c][s]);
                    }
                }
            }
        }
    }

    #pragma unroll
    for (int c = 0; c < CT; c++) {
        float* op = out + (((long)n * COUT + co0 + c) * HOUT + oy) * HOUT + ox0;
        if (ST == 4) {
            float4 v;
            v.x = RELU ? fmaxf(acc[c][0], 0.f) : acc[c][0];
            v.y = RELU ? fmaxf(acc[c][1], 0.f) : acc[c][1];
            v.z = RELU ? fmaxf(acc[c][2], 0.f) : acc[c][2];
            v.w = RELU ? fmaxf(acc[c][3], 0.f) : acc[c][3];
            *(float4*)op = v;
        } else {
            #pragma unroll
            for (int s = 0; s < ST; s++)
                op[s] = RELU ? fmaxf(acc[c][s], 0.f) : acc[c][s];
        }
    }
}

// ------------------- register-tiled transposed conv k=4 s=2 p=1 -------------------
// Output decomposed by column parity: a thread handles ST same-parity columns of
// one output row, so its 4 taps (ky0,kx0 combos) are fixed. w is torch layout
// [CIN, COUT, 4, 4]. Per ci: 2*(ST+1) input loads + 4*CT smem reads -> 4*CT*ST FMAs.
template<int CIN, int HIN, int COUT, int CT, int ST, bool RELU, bool SIG>
__global__ void k_deconvt(const float* __restrict__ in, const float* __restrict__ w,
                          const float* __restrict__ bias, float* __restrict__ out) {
    constexpr int HOUT = 2 * HIN;
    constexpr int G = HIN / ST;         // same-parity column groups per row
    __shared__ float sw[CIN * CT * 16];
    const int co0 = blockIdx.y * CT;
    const int n   = blockIdx.z;
    const int t   = threadIdx.x;
    for (int i = t; i < CIN * CT * 16; i += 256) {
        int ci = i / (CT * 16), c = (i / 16) % CT, kk = i & 15;
        sw[i] = w[((long)ci * COUT + co0 + c) * 16 + kk];
    }
    __syncthreads();

    const int tp = blockIdx.x * 256 + t;
    const int oy = tp / (2 * G);
    const int r  = tp % (2 * G);
    const int px = r & 1;
    const int g  = r >> 1;
    const int ky0 = (oy + 1) & 1;
    const int kx0 = 1 - px;
    const int iyA = (oy + 1 - ky0) >> 1;   // may be HIN at last row
    const int iyB = iyA - 1;               // may be -1 at first row
    const bool vA = iyA < HIN;
    const bool vB = iyB >= 0;
    const int cb0 = g * ST + px - 1;       // cols cb0 .. cb0+ST needed

    const int i00 = ky0 * 4 + kx0;
    const int i01 = i00 + 2;
    const int i10 = i00 + 8;
    const int i11 = i10 + 2;

    float acc[CT][ST];
    #pragma unroll
    for (int c = 0; c < CT; c++) {
        float bv = bias[co0 + c];
        #pragma unroll
        for (int s = 0; s < ST; s++) acc[c][s] = bv;
    }

    for (int ci = 0; ci < CIN; ci++) {
        const float* ic = in + ((long)n * CIN + ci) * HIN * HIN;
        float xA[ST + 1], xB[ST + 1];
        #pragma unroll
        for (int j = 0; j <= ST; j++) {
            int col = cb0 + j;
            bool vc = (unsigned)col < (unsigned)HIN;
            xA[j] = (vA && vc) ? ic[iyA * HIN + col] : 0.f;
            xB[j] = (vB && vc) ? ic[iyB * HIN + col] : 0.f;
        }
        const float* wb = sw + ci * CT * 16;
        #pragma unroll
        for (int c = 0; c < CT; c++) {
            float wA0 = wb[c * 16 + i00];
            float wA1 = wb[c * 16 + i01];
            float wB0 = wb[c * 16 + i10];
            float wB1 = wb[c * 16 + i11];
            #pragma unroll
            for (int s = 0; s < ST; s++) {
                float v = acc[c][s];
                v = fmaf(xA[s + 1], wA0, v);
                v = fmaf(xA[s],     wA1, v);
                v = fmaf(xB[s + 1], wB0, v);
                v = fmaf(xB[s],     wB1, v);
                acc[c][s] = v;
            }
        }
    }

    #pragma unroll
    for (int c = 0; c < CT; c++) {
        #pragma unroll
        for (int s = 0; s < ST; s++) {
            int ox = 2 * (g * ST + s) + px;
            float v = acc[c][s];
            if (RELU) v = fmaxf(v, 0.f);
            if (SIG)  v = 1.f / (1.f + expf(-v));
            out[(((long)n * COUT + co0 + c) * HOUT + oy) * HOUT + ox] = v;
        }
    }
}

// ------------------- vector quantization -------------------
// 2 latent positions per thread (float2 z loads/q stores), codebook streamed
// through shared in 4 chunks of 128 codewords, read as float4 (LDS.128).
// dist = ||c||^2 - 2 z.c ; strict < keeps first-min tie semantics.
__global__ void k_vq(const float* __restrict__ z, const float* __restrict__ cb,
                     float* __restrict__ q, float* __restrict__ lpart) {
    __shared__ float scb[128 * 32];
    __shared__ float scn[128];
    __shared__ float red[256];
    const int t    = threadIdx.x;
    const int pos0 = (blockIdx.x * 256 + t) * 2;  // even; both positions same image
    const int n    = pos0 >> 10;
    const int p0   = pos0 & 1023;

    const float* zp = z + (long)n * 32 * 1024 + p0;
    float zv0[32], zv1[32];
    #pragma unroll
    for (int d = 0; d < 32; d++) {
        float2 v = *(const float2*)(zp + d * 1024);
        zv0[d] = v.x; zv1[d] = v.y;
    }

    float best0 = 3.4e38f, best1 = 3.4e38f;
    int   bi0 = 0, bi1 = 0;
    for (int ch = 0; ch < 4; ch++) {
        __syncthreads();
        for (int i = t; i < 4096; i += 256) scb[i] = cb[ch * 4096 + i];
        __syncthreads();
        if (t < 128) {
            float s = 0.f;
            const float* c = scb + t * 32;
            #pragma unroll
            for (int d = 0; d < 32; d++) s = fmaf(c[d], c[d], s);
            scn[t] = s;
        }
        __syncthreads();
        for (int k = 0; k < 128; k++) {
            const float4* c4 = (const float4*)(scb + k * 32);
            float dot0 = 0.f, dot1 = 0.f;
            #pragma unroll
            for (int j = 0; j < 8; j++) {
                float4 c = c4[j];
                int d = j * 4;
                dot0 = fmaf(zv0[d], c.x, dot0); dot1 = fmaf(zv1[d], c.x, dot1);
                dot0 = fmaf(zv0[d+1], c.y, dot0); dot1 = fmaf(zv1[d+1], c.y, dot1);
                dot0 = fmaf(zv0[d+2], c.z, dot0); dot1 = fmaf(zv1[d+2], c.z, dot1);
                dot0 = fmaf(zv0[d+3], c.w, dot0); dot1 = fmaf(zv1[d+3], c.w, dot1);
            }
            float nk = scn[k];
            float d0 = fmaf(-2.f, dot0, nk);
            float d1 = fmaf(-2.f, dot1, nk);
            if (d0 < best0) { best0 = d0; bi0 = ch * 128 + k; }
            if (d1 < best1) { best1 = d1; bi1 = ch * 128 + k; }
        }
    }

    float lsum = 0.f;
    const float* c0 = cb + bi0 * 32;
    const float* c1 = cb + bi1 * 32;
    float* qp = q + (long)n * 32 * 1024 + p0;
    #pragma unroll
    for (int d = 0; d < 32; d++) {
        float q0 = __ldg(c0 + d);
        float q1 = __ldg(c1 + d);
        *(float2*)(qp + d * 1024) = make_float2(q0, q1);
        float e0 = q0 - zv0[d], e1 = q1 - zv1[d];
        lsum = fmaf(e0, e0, lsum);
        lsum = fmaf(e1, e1, lsum);
    }

    red[t] = lsum;
    __syncthreads();
    for (int s = 128; s > 0; s >>= 1) {
        if (t < s) red[t] += red[t + s];
        __syncthreads();
    }
    if (t == 0) lpart[blockIdx.x] = red[0];
}

// deterministic fixed-order final reduction: vq_loss = 1.26 * mean
__global__ void k_loss(const float* __restrict__ lpart, float* __restrict__ out,
                       int out_size) {
    __shared__ float red[256];
    const int t = threadIdx.x;
    red[t] = lpart[t] + lpart[t + 256];
    __syncthreads();
    for (int s = 128; s > 0; s >>= 1) {
        if (t < s) red[t] += red[t + s];
        __syncthreads();
    }
    if (t == 0) out[out_size - 1] = 1.26f * red[0] / 8388608.0f;
}

// ------------------- launch -------------------
extern "C" void kernel_launch(void* const* d_in, const int* in_sizes, int n_in,
                              void* d_out, int out_size) {
    const float* x   = (const float*)d_in[0];
    const float* ew1 = (const float*)d_in[1];  const float* eb1 = (const float*)d_in[2];
    const float* ew2 = (const float*)d_in[3];  const float* eb2 = (const float*)d_in[4];
    const float* ew3 = (const float*)d_in[5];  const float* eb3 = (const float*)d_in[6];
    const float* ew4 = (const float*)d_in[7];  const float* eb4 = (const float*)d_in[8];
    const float* cb  = (const float*)d_in[9];
    const float* dw1 = (const float*)d_in[10]; const float* db1 = (const float*)d_in[11];
    const float* tw1 = (const float*)d_in[12]; const float* tb1 = (const float*)d_in[13];
    const float* tw2 = (const float*)d_in[14]; const float* tb2 = (const float*)d_in[15];
    float* out = (float*)d_out;

    float *pa, *pb, *pc, *pz, *pq, *pl;
    cudaGetSymbolAddress((void**)&pa, g_a);
    cudaGetSymbolAddress((void**)&pb, g_b);
    cudaGetSymbolAddress((void**)&pc, g_c);
    cudaGetSymbolAddress((void**)&pz, g_z);
    cudaGetSymbolAddress((void**)&pq, g_q);
    cudaGetSymbolAddress((void**)&pl, g_lpart);

    // Encoder
    k_convt<1, 128, 4, 2, 1, 32, 8, 4, true ><<<dim3(4, 4, BATCH), 256>>>(x,  ew1, eb1, pa); // ->[256,32,64,64]
    k_convt<32, 64, 4, 2, 1, 64, 8, 4, true ><<<dim3(1, 8, BATCH), 256>>>(pa, ew2, eb2, pb); // ->[256,64,32,32]
    k_convt<64, 32, 3, 1, 1, 64, 8, 4, true ><<<dim3(1, 8, BATCH), 256>>>(pb, ew3, eb3, pc); // ->[256,64,32,32]
    k_convt<64, 32, 1, 1, 0, 32, 8, 4, false><<<dim3(1, 4, BATCH), 256>>>(pc, ew4, eb4, pz); // ->[256,32,32,32]

    // Vector quantization (+ per-block loss partials)
    k_vq<<<512, 256>>>(pz, cb, pq, pl);

    // Decoder
    k_convt<32, 32, 3, 1, 1, 64, 8, 4, true ><<<dim3(1, 8, BATCH), 256>>>(pq, dw1, db1, pc); // ->[256,64,32,32]
    k_deconvt<64, 32, 32, 8, 4, true,  false><<<dim3(4, 4, BATCH), 256>>>(pc, tw1, tb1, pa); // ->[256,32,64,64]
    k_deconvt<32, 64,  1, 1, 8, false, true ><<<dim3(8, 1, BATCH), 256>>>(pa, tw2, tb2, out);// ->[256,1,128,128]

    // Deterministic loss finalize into out[out_size-1]
    k_loss<<<1, 256>>>(pl, out, out_size);
}

// round 3
// speedup vs baseline: 6.6511x; 1.6233x over previous
#include <cuda_runtime.h>
#include <math.h>

#define BATCH 256

// ------------------- scratch (alloc-free rule: device globals) -------------------
__device__ float g_a[BATCH * 32 * 64 * 64];   // conv1 out / deconv1 out
__device__ float g_b[BATCH * 64 * 32 * 32];   // conv2 out
__device__ float g_c[BATCH * 64 * 32 * 32];   // conv3 out / dec1 out
__device__ float g_z[BATCH * 32 * 32 * 32];   // encoder latent z
__device__ float g_q[BATCH * 32 * 32 * 32];   // quantized latent
__device__ float g_lpart[512];                // per-block loss partials
__device__ float g_wb[131072];                // pre-transposed weights [K][COUT]

// weight-prep offsets into g_wb
#define OFF_C2  0        // conv2 : 16*32*64 = 32768
#define OFF_C3  32768    // conv3 : 9*64*64  = 36864
#define OFF_C4  69632    // conv4 : 1*64*32  = 2048
#define OFF_D1  71680    // dec1  : 9*32*64  = 18432
#define OFF_T1  90112    // deconv1: 4cls*4*64*32 = 32768

// ------------------- tf32 helpers -------------------
__device__ __forceinline__ unsigned f2tf32(float x) {
    unsigned r;
    asm("cvt.rna.tf32.f32 %0, %1;" : "=r"(r) : "f"(x));
    return r;
}

__device__ __forceinline__ void mma_tf32(float& c0, float& c1, float& c2, float& c3,
                                         unsigned a0, unsigned a1, unsigned a2, unsigned a3,
                                         unsigned b0, unsigned b1) {
    asm volatile("mma.sync.aligned.m16n8k8.row.col.f32.tf32.tf32.f32 "
                 "{%0,%1,%2,%3}, {%4,%5,%6,%7}, {%8,%9}, {%0,%1,%2,%3};"
                 : "+f"(c0), "+f"(c1), "+f"(c2), "+f"(c3)
                 : "r"(a0), "r"(a1), "r"(a2), "r"(a3), "r"(b0), "r"(b1));
}

// ------------------- weight prep -------------------
// OIHW -> Bp[(tap*CIN+ci)*COUT+co], tap row-major over (ky,kx)
template<int CIN, int COUT, int KK>
__global__ void k_prep_oihw(const float* __restrict__ w, float* __restrict__ bp) {
    int i = blockIdx.x * 256 + threadIdx.x;
    if (i >= KK * CIN * COUT) return;
    int co = i % COUT; int r = i / COUT; int ci = r % CIN; int tap = r / CIN;
    bp[i] = w[(co * CIN + ci) * KK + tap];
}

// torch deconv [CIN,COUT,4,4] -> per parity class Bp[cls][(j*CIN+ci)*COUT+co]
// class cls=(py,px); tap j=(ty,tx): dy=py-ty, dx=px-tx; ky = ty?3-py:1-py, kx likewise.
template<int CIN, int COUT>
__global__ void k_prep_deconv(const float* __restrict__ w, float* __restrict__ bp) {
    int i = blockIdx.x * 256 + threadIdx.x;
    if (i >= 16 * CIN * COUT) return;
    int co = i % COUT; int r = i / COUT; int ci = r % CIN; int jt = r / CIN;
    int cls = jt >> 2, j = jt & 3;
    int py = cls >> 1, px = cls & 1;
    int ty = j >> 1, tx = j & 1;
    int ky = ty ? 3 - py : 1 - py;
    int kx = tx ? 3 - px : 1 - px;
    bp[i] = w[(ci * COUT + co) * 16 + ky * 4 + kx];
}

// ------------------- tf32 implicit-GEMM conv -------------------
// Logical output grid is always 32x32 per image (M=1024/image, 128 per block).
// A: im2col tile [8k][128m] staged in smem; B: prepped [K][COUT] chunks.
// X3: 3xTF32 (hi/lo split) for ~fp32 accuracy (encoder path).
// DECONV: 4 parity classes via blockIdx.y; output written strided (OS=2) into W-wide map.
template<int CIN, int HIN, int COUT, int S, int KW, int NTAPS, int P,
         bool DECONV, int OS, int W, bool X3, bool RELU>
__global__ void k_igemm(const float* __restrict__ in, const float* __restrict__ wb,
                        const float* __restrict__ bias, float* __restrict__ out) {
    constexpr int NS = X3 ? 2 : 1;
    constexpr int CI8 = CIN / 8;
    constexpr int NC = NTAPS * CI8;
    constexpr int SZ_A = NS * 8 * 136 * 4;
    constexpr int SZ_B = NS * 8 * 72 * 4;
    constexpr int SZ_C = 128 * 65 * 4;
    constexpr int SZ = (SZ_A + SZ_B > SZ_C) ? (SZ_A + SZ_B) : SZ_C;
    __shared__ __align__(16) unsigned char smem[SZ];
    typedef unsigned (*APtr)[8][136];
    typedef unsigned (*BPtr)[8][72];
    APtr As = reinterpret_cast<APtr>(smem);
    BPtr Bs = reinterpret_cast<BPtr>(smem + SZ_A);
    float (*Cs)[65] = reinterpret_cast<float(*)[65]>(smem);

    const int t = threadIdx.x;
    const int lane = t & 31;
    const int wrp = t >> 5;
    const int n = blockIdx.z;
    const int m0 = blockIdx.x * 128;

    int py = 0, px = 0;
    const float* wbp = wb;
    if (DECONV) {
        int cls = blockIdx.y;
        py = cls >> 1; px = cls & 1;
        wbp += cls * NTAPS * CIN * COUT;
    }

    float acc[COUT / 8][4];
    #pragma unroll
    for (int i = 0; i < COUT / 8; i++)
        #pragma unroll
        for (int j = 0; j < 4; j++) acc[i][j] = 0.f;

    const int g  = lane >> 2;
    const int tg = lane & 3;
    const int mw = wrp * 16;

    for (int chunk = 0; chunk < NC; chunk++) {
        const int tap = chunk / CI8;
        const int ci0 = (chunk % CI8) * 8;
        int dy, dx;
        if (DECONV) { dy = py - (tap >> 1); dx = px - (tap & 1); }
        else        { dy = tap / KW - P;    dx = tap % KW - P; }
        __syncthreads();
        // stage A (each thread: one k-row, 4 m-values)
        {
            const int ci = ci0 + wrp;
            const float* base = in + ((long)n * CIN + ci) * HIN * HIN;
            #pragma unroll
            for (int j = 0; j < 4; j++) {
                int m = j * 32 + lane;
                int p = m0 + m;
                int oy = p >> 5, ox = p & 31;
                int iy = oy * S + dy, ix = ox * S + dx;
                float v = ((unsigned)iy < (unsigned)HIN && (unsigned)ix < (unsigned)HIN)
                          ? base[iy * HIN + ix] : 0.f;
                unsigned hi = f2tf32(v);
                As[0][wrp][m] = hi;
                if (X3) As[1][wrp][m] = f2tf32(v - __uint_as_float(hi));
            }
        }
        // stage B
        for (int i = t; i < 8 * COUT; i += 256) {
            int bk = i / COUT, co = i % COUT;
            float v = wbp[(tap * CIN + ci0 + bk) * COUT + co];
            unsigned hi = f2tf32(v);
            Bs[0][bk][co] = hi;
            if (X3) Bs[1][bk][co] = f2tf32(v - __uint_as_float(hi));
        }
        __syncthreads();
        // compute: warp owns m-tile [mw, mw+16), all N
        unsigned ah0 = As[0][tg][mw + g],     ah1 = As[0][tg][mw + g + 8];
        unsigned ah2 = As[0][tg + 4][mw + g], ah3 = As[0][tg + 4][mw + g + 8];
        unsigned al0 = 0, al1 = 0, al2 = 0, al3 = 0;
        if (X3) {
            al0 = As[1][tg][mw + g];     al1 = As[1][tg][mw + g + 8];
            al2 = As[1][tg + 4][mw + g]; al3 = As[1][tg + 4][mw + g + 8];
        }
        #pragma unroll
        for (int nt = 0; nt < COUT / 8; nt++) {
            unsigned bh0 = Bs[0][tg][nt * 8 + g];
            unsigned bh1 = Bs[0][tg + 4][nt * 8 + g];
            if (X3) {
                unsigned bl0 = Bs[1][tg][nt * 8 + g];
                unsigned bl1 = Bs[1][tg + 4][nt * 8 + g];
                mma_tf32(acc[nt][0], acc[nt][1], acc[nt][2], acc[nt][3],
                         al0, al1, al2, al3, bh0, bh1);
                mma_tf32(acc[nt][0], acc[nt][1], acc[nt][2], acc[nt][3],
                         ah0, ah1, ah2, ah3, bl0, bl1);
            }
            mma_tf32(acc[nt][0], acc[nt][1], acc[nt][2], acc[nt][3],
                     ah0, ah1, ah2, ah3, bh0, bh1);
        }
    }

    __syncthreads();
    // frags -> smem
    #pragma unroll
    for (int nt = 0; nt < COUT / 8; nt++) {
        Cs[mw + g][nt * 8 + 2 * tg]         = acc[nt][0];
        Cs[mw + g][nt * 8 + 2 * tg + 1]     = acc[nt][1];
        Cs[mw + g + 8][nt * 8 + 2 * tg]     = acc[nt][2];
        Cs[mw + g + 8][nt * 8 + 2 * tg + 1] = acc[nt][3];
    }
    __syncthreads();
    // bias + act + store
    for (int i = t; i < 32 * COUT; i += 256) {
        int co = i >> 5;
        int m = (i & 31) * 4;
        float bv = __ldg(bias + co);
        float v0 = Cs[m][co] + bv, v1 = Cs[m + 1][co] + bv;
        float v2 = Cs[m + 2][co] + bv, v3 = Cs[m + 3][co] + bv;
        if (RELU) {
            v0 = fmaxf(v0, 0.f); v1 = fmaxf(v1, 0.f);
            v2 = fmaxf(v2, 0.f); v3 = fmaxf(v3, 0.f);
        }
        int p = m0 + m;
        int oy = p >> 5, ox = p & 31;
        float* ob = out + (((long)n * COUT + co) * W + oy * OS + py) * W + ox * OS + px;
        if (OS == 1) {
            *(float4*)ob = make_float4(v0, v1, v2, v3);
        } else {
            ob[0] = v0; ob[2] = v1; ob[4] = v2; ob[6] = v3;
        }
    }
}

// ------------------- conv1 (scalar, K tiny / memory-ish) -------------------
template<int CIN, int HIN, int K, int S, int P, int COUT, int CT, int ST, bool RELU>
__global__ void k_convt(const float* __restrict__ in, const float* __restrict__ w,
                        const float* __restrict__ bias, float* __restrict__ out) {
    constexpr int HOUT = (HIN + 2 * P - K) / S + 1;
    constexpr int KK = K * K;
    __shared__ float sw[CT * CIN * KK];
    const int co0 = blockIdx.y * CT;
    const int n   = blockIdx.z;
    const int t   = threadIdx.x;
    for (int i = t; i < CT * CIN * KK; i += 256) {
        int c = i / (CIN * KK), rest = i % (CIN * KK);
        sw[i] = w[(co0 + c) * CIN * KK + rest];
    }
    __syncthreads();

    const int p0  = (blockIdx.x * 256 + t) * ST;
    const int oy  = p0 / HOUT;
    const int ox0 = p0 % HOUT;

    float acc[CT][ST];
    #pragma unroll
    for (int c = 0; c < CT; c++) {
        float bv = bias[co0 + c];
        #pragma unroll
        for (int s = 0; s < ST; s++) acc[c][s] = bv;
    }

    const float* ib = in + (long)n * CIN * HIN * HIN;
    for (int ci = 0; ci < CIN; ci++) {
        const float* ic = ib + ci * HIN * HIN;
        #pragma unroll
        for (int ky = 0; ky < K; ky++) {
            int iy = oy * S - P + ky;
            if ((unsigned)iy < (unsigned)HIN) {
                const float* row = ic + iy * HIN;
                #pragma unroll
                for (int kx = 0; kx < K; kx++) {
                    float xv[ST];
                    #pragma unroll
                    for (int s = 0; s < ST; s++) {
                        int ix = (ox0 + s) * S - P + kx;
                        xv[s] = ((unsigned)ix < (unsigned)HIN) ? row[ix] : 0.f;
                    }
                    #pragma unroll
                    for (int c = 0; c < CT; c++) {
                        float wv = sw[(c * CIN + ci) * KK + ky * K + kx];
                        #pragma unroll
                        for (int s = 0; s < ST; s++)
                            acc[c][s] = fmaf(xv[s], wv, acc[c][s]);
                    }
                }
            }
        }
    }

    #pragma unroll
    for (int c = 0; c < CT; c++) {
        float* op = out + (((long)n * COUT + co0 + c) * HOUT + oy) * HOUT + ox0;
        #pragma unroll
        for (int s = 0; s < ST; s++)
            op[s] = RELU ? fmaxf(acc[c][s], 0.f) : acc[c][s];
    }
}

// ------------------- deconv2: [256,32,64,64] -> [256,1,128,128], sigmoid -------------------
// Thread computes a 4x8 output block (both parities in y and x). Per ci:
// 24 input loads (float4 middle) + 16 weight regs -> 128 FMAs.
__global__ void k_deconv2(const float* __restrict__ in, const float* __restrict__ w,
                          const float* __restrict__ bias, float* __restrict__ out) {
    __shared__ float sw[512];
    const int t = threadIdx.x;
    const int n = blockIdx.z;
    for (int i = t; i < 512; i += 256) sw[i] = w[i];
    __syncthreads();

    const int ti = blockIdx.x * 256 + t;      // 0..511
    const int ty = ti >> 4, tx = ti & 15;
    const float bv = __ldg(bias);

    float acc[4][8];
    #pragma unroll
    for (int r = 0; r < 4; r++)
        #pragma unroll
        for (int c = 0; c < 8; c++) acc[r][c] = 0.f;

    const float* ib = in + (long)n * 32 * 4096;
    for (int ci = 0; ci < 32; ci++) {
        const float* ic = ib + ci * 4096;
        float xv[4][6];
        #pragma unroll
        for (int rr = 0; rr < 4; rr++) {
            int iy = 2 * ty - 1 + rr;
            bool vy = (unsigned)iy < 64u;
            const float* row = ic + iy * 64;
            int c0 = 4 * tx - 1;
            xv[rr][0] = (vy && c0 >= 0) ? row[c0] : 0.f;
            if (vy) {
                float4 m4 = *(const float4*)(row + 4 * tx);
                xv[rr][1] = m4.x; xv[rr][2] = m4.y; xv[rr][3] = m4.z; xv[rr][4] = m4.w;
            } else {
                xv[rr][1] = xv[rr][2] = xv[rr][3] = xv[rr][4] = 0.f;
            }
            int c5 = 4 * tx + 4;
            xv[rr][5] = (vy && c5 < 64) ? row[c5] : 0.f;
        }
        float wr[16];
        #pragma unroll
        for (int k = 0; k < 16; k++) wr[k] = sw[ci * 16 + k];
        #pragma unroll
        for (int r = 0; r < 4; r++) {
            const int pyy = r & 1;
            const int rowA = (r >> 1) + pyy + 1, rowB = rowA - 1;
            #pragma unroll
            for (int c = 0; c < 8; c++) {
                const int pxx = c & 1;
                const int colA = (c >> 1) + pxx + 1, colB = colA - 1;
                float a = acc[r][c];
                a = fmaf(xv[rowA][colA], wr[(1 - pyy) * 4 + (1 - pxx)], a);
                a = fmaf(xv[rowA][colB], wr[(1 - pyy) * 4 + (3 - pxx)], a);
                a = fmaf(xv[rowB][colA], wr[(3 - pyy) * 4 + (1 - pxx)], a);
                a = fmaf(xv[rowB][colB], wr[(3 - pyy) * 4 + (3 - pxx)], a);
                acc[r][c] = a;
            }
        }
    }

    float* ob = out + (long)n * 16384;
    #pragma unroll
    for (int r = 0; r < 4; r++) {
        int oy = 4 * ty + r;
        float v[8];
        #pragma unroll
        for (int c = 0; c < 8; c++)
            v[c] = 1.f / (1.f + expf(-(acc[r][c] + bv)));
        *(float4*)(ob + oy * 128 + 8 * tx)     = make_float4(v[0], v[1], v[2], v[3]);
        *(float4*)(ob + oy * 128 + 8 * tx + 4) = make_float4(v[4], v[5], v[6], v[7]);
    }
}

// ------------------- vector quantization (fp32, argmin exactness preserved) -------------------
__global__ void k_vq(const float* __restrict__ z, const float* __restrict__ cb,
                     float* __restrict__ q, float* __restrict__ lpart) {
    __shared__ float scb[128 * 32];
    __shared__ float scn[128];
    __shared__ float red[256];
    const int t    = threadIdx.x;
    const int pos0 = (blockIdx.x * 256 + t) * 2;
    const int n    = pos0 >> 10;
    const int p0   = pos0 & 1023;

    const float* zp = z + (long)n * 32 * 1024 + p0;
    float zv0[32], zv1[32];
    #pragma unroll
    for (int d = 0; d < 32; d++) {
        float2 v = *(const float2*)(zp + d * 1024);
        zv0[d] = v.x; zv1[d] = v.y;
    }

    float best0 = 3.4e38f, best1 = 3.4e38f;
    int bi0 = 0, bi1 = 0;
    for (int ch = 0; ch < 4; ch++) {
        __syncthreads();
        for (int i = t; i < 4096; i += 256) scb[i] = cb[ch * 4096 + i];
        __syncthreads();
        if (t < 128) {
            float s = 0.f;
            const float* c = scb + t * 32;
            #pragma unroll
            for (int d = 0; d < 32; d++) s = fmaf(c[d], c[d], s);
            scn[t] = s;
        }
        __syncthreads();
        for (int k = 0; k < 128; k++) {
            const float4* c4 = (const float4*)(scb + k * 32);
            float dot0 = 0.f, dot1 = 0.f;
            #pragma unroll
            for (int j = 0; j < 8; j++) {
                float4 c = c4[j];
                int d = j * 4;
                dot0 = fmaf(zv0[d], c.x, dot0);     dot1 = fmaf(zv1[d], c.x, dot1);
                dot0 = fmaf(zv0[d + 1], c.y, dot0); dot1 = fmaf(zv1[d + 1], c.y, dot1);
                dot0 = fmaf(zv0[d + 2], c.z, dot0); dot1 = fmaf(zv1[d + 2], c.z, dot1);
                dot0 = fmaf(zv0[d + 3], c.w, dot0); dot1 = fmaf(zv1[d + 3], c.w, dot1);
            }
            float nk = scn[k];
            float d0 = fmaf(-2.f, dot0, nk);
            float d1 = fmaf(-2.f, dot1, nk);
            if (d0 < best0) { best0 = d0; bi0 = ch * 128 + k; }
            if (d1 < best1) { best1 = d1; bi1 = ch * 128 + k; }
        }
    }

    float lsum = 0.f;
    const float* c0 = cb + bi0 * 32;
    const float* c1 = cb + bi1 * 32;
    float* qp = q + (long)n * 32 * 1024 + p0;
    #pragma unroll
    for (int d = 0; d < 32; d++) {
        float q0 = __ldg(c0 + d);
        float q1 = __ldg(c1 + d);
        *(float2*)(qp + d * 1024) = make_float2(q0, q1);
        float e0 = q0 - zv0[d], e1 = q1 - zv1[d];
        lsum = fmaf(e0, e0, lsum);
        lsum = fmaf(e1, e1, lsum);
    }

    red[t] = lsum;
    __syncthreads();
    for (int s = 128; s > 0; s >>= 1) {
        if (t < s) red[t] += red[t + s];
        __syncthreads();
    }
    if (t == 0) lpart[blockIdx.x] = red[0];
}

__global__ void k_loss(const float* __restrict__ lpart, float* __restrict__ out,
                       int out_size) {
    __shared__ float red[256];
    const int t = threadIdx.x;
    red[t] = lpart[t] + lpart[t + 256];
    __syncthreads();
    for (int s = 128; s > 0; s >>= 1) {
        if (t < s) red[t] += red[t + s];
        __syncthreads();
    }
    if (t == 0) out[out_size - 1] = 1.26f * red[0] / 8388608.0f;
}

// ------------------- launch -------------------
extern "C" void kernel_launch(void* const* d_in, const int* in_sizes, int n_in,
                              void* d_out, int out_size) {
    const float* x   = (const float*)d_in[0];
    const float* ew1 = (const float*)d_in[1];  const float* eb1 = (const float*)d_in[2];
    const float* ew2 = (const float*)d_in[3];  const float* eb2 = (const float*)d_in[4];
    const float* ew3 = (const float*)d_in[5];  const float* eb3 = (const float*)d_in[6];
    const float* ew4 = (const float*)d_in[7];  const float* eb4 = (const float*)d_in[8];
    const float* cb  = (const float*)d_in[9];
    const float* dw1 = (const float*)d_in[10]; const float* db1 = (const float*)d_in[11];
    const float* tw1 = (const float*)d_in[12]; const float* tb1 = (const float*)d_in[13];
    const float* tw2 = (const float*)d_in[14]; const float* tb2 = (const float*)d_in[15];
    float* out = (float*)d_out;

    float *pa, *pb, *pc, *pz, *pq, *pl, *pwb;
    cudaGetSymbolAddress((void**)&pa, g_a);
    cudaGetSymbolAddress((void**)&pb, g_b);
    cudaGetSymbolAddress((void**)&pc, g_c);
    cudaGetSymbolAddress((void**)&pz, g_z);
    cudaGetSymbolAddress((void**)&pq, g_q);
    cudaGetSymbolAddress((void**)&pl, g_lpart);
    cudaGetSymbolAddress((void**)&pwb, g_wb);

    // weight prep (tiny)
    k_prep_oihw<32, 64, 16><<<(16 * 32 * 64 + 255) / 256, 256>>>(ew2, pwb + OFF_C2);
    k_prep_oihw<64, 64, 9 ><<<(9 * 64 * 64 + 255) / 256, 256>>>(ew3, pwb + OFF_C3);
    k_prep_oihw<64, 32, 1 ><<<(1 * 64 * 32 + 255) / 256, 256>>>(ew4, pwb + OFF_C4);
    k_prep_oihw<32, 64, 9 ><<<(9 * 32 * 64 + 255) / 256, 256>>>(dw1, pwb + OFF_D1);
    k_prep_deconv<64, 32><<<(16 * 64 * 32 + 255) / 256, 256>>>(tw1, pwb + OFF_T1);

    // Encoder
    k_convt<1, 128, 4, 2, 1, 32, 8, 4, true><<<dim3(4, 4, BATCH), 256>>>(x, ew1, eb1, pa);
    // conv2: 3xTF32, CIN=32 HIN=64 COUT=64 S=2 K=4 P=1
    k_igemm<32, 64, 64, 2, 4, 16, 1, false, 1, 32, true, true>
        <<<dim3(8, 1, BATCH), 256>>>(pa, pwb + OFF_C2, eb2, pb);
    // conv3: 3xTF32, CIN=64 HIN=32 COUT=64 K=3 P=1
    k_igemm<64, 32, 64, 1, 3, 9, 1, false, 1, 32, true, true>
        <<<dim3(8, 1, BATCH), 256>>>(pb, pwb + OFF_C3, eb3, pc);
    // conv4: 3xTF32, 1x1, COUT=32, no relu
    k_igemm<64, 32, 32, 1, 1, 1, 0, false, 1, 32, true, false>
        <<<dim3(8, 1, BATCH), 256>>>(pc, pwb + OFF_C4, eb4, pz);

    // Vector quantization (fp32)
    k_vq<<<512, 256>>>(pz, cb, pq, pl);

    // Decoder
    // dec1: tf32, CIN=32 HIN=32 COUT=64 K=3 P=1
    k_igemm<32, 32, 64, 1, 3, 9, 1, false, 1, 32, false, true>
        <<<dim3(8, 1, BATCH), 256>>>(pq, pwb + OFF_D1, db1, pc);
    // deconv1: tf32, 4 parity classes, CIN=64 HIN=32 COUT=32, out 64x64 strided
    k_igemm<64, 32, 32, 1, 1, 4, 0, true, 2, 64, false, true>
        <<<dim3(8, 4, BATCH), 256>>>(pc, pwb + OFF_T1, tb1, pa);
    // deconv2: scalar blocked + sigmoid
    k_deconv2<<<dim3(2, 1, BATCH), 256>>>(pa, tw2, tb2, out);

    // loss
    k_loss<<<1, 256>>>(pl, out, out_size);
}

// round 4
// speedup vs baseline: 7.7979x; 1.1724x over previous
#include <cuda_runtime.h>
#include <math.h>

#define BATCH 256

// ------------------- scratch (alloc-free rule: device globals) -------------------
__device__ float g_a[BATCH * 32 * 64 * 64];   // conv1 out / deconv1 out
__device__ float g_b[BATCH * 64 * 32 * 32];   // conv2 out
__device__ float g_c[BATCH * 64 * 32 * 32];   // conv3 out / dec1 out
__device__ float g_z[BATCH * 32 * 32 * 32];   // encoder latent z
__device__ float g_q[BATCH * 32 * 32 * 32];   // quantized latent
__device__ float g_lpart[2048];               // per-block loss partials
__device__ float g_wb[131072];                // pre-transposed weights [K][COUT]
__device__ float g_cn[512];                   // codebook norms

// weight-prep offsets into g_wb
#define OFF_C2  0        // conv2 : 16*32*64 = 32768
#define OFF_C3  32768    // conv3 : 9*64*64  = 36864
#define OFF_C4  69632    // conv4 : 1*64*32  = 2048
#define OFF_D1  71680    // dec1  : 9*32*64  = 18432
#define OFF_T1  90112    // deconv1: 4cls*4*64*32 = 32768

// ------------------- tf32 helpers -------------------
__device__ __forceinline__ unsigned f2tf32(float x) {
    unsigned r;
    asm("cvt.rna.tf32.f32 %0, %1;" : "=r"(r) : "f"(x));
    return r;
}

__device__ __forceinline__ void mma_tf32(float& c0, float& c1, float& c2, float& c3,
                                         unsigned a0, unsigned a1, unsigned a2, unsigned a3,
                                         unsigned b0, unsigned b1) {
    asm volatile("mma.sync.aligned.m16n8k8.row.col.f32.tf32.tf32.f32 "
                 "{%0,%1,%2,%3}, {%4,%5,%6,%7}, {%8,%9}, {%0,%1,%2,%3};"
                 : "+f"(c0), "+f"(c1), "+f"(c2), "+f"(c3)
                 : "r"(a0), "r"(a1), "r"(a2), "r"(a3), "r"(b0), "r"(b1));
}

// ------------------- fused weight prep + codebook norms -------------------
__global__ void k_prep_all(const float* __restrict__ ew2, const float* __restrict__ ew3,
                           const float* __restrict__ ew4, const float* __restrict__ dw1,
                           const float* __restrict__ tw1, const float* __restrict__ cb,
                           float* __restrict__ wb, float* __restrict__ cn) {
    const int b = blockIdx.x, t = threadIdx.x;
    if (b < 128) {                       // conv2: KK=16 CIN=32 COUT=64
        int i = b * 256 + t;
        int co = i & 63, r = i >> 6, ci = r & 31, tap = r >> 5;
        wb[OFF_C2 + i] = ew2[(co * 32 + ci) * 16 + tap];
    } else if (b < 272) {                // conv3: KK=9 CIN=64 COUT=64 (36864)
        int i = (b - 128) * 256 + t;
        int co = i & 63, r = i >> 6, ci = r & 63, tap = r >> 6;
        wb[OFF_C3 + i] = ew3[(co * 64 + ci) * 9 + tap];
    } else if (b < 280) {                // conv4: 1x1 CIN=64 COUT=32 (2048)
        int i = (b - 272) * 256 + t;
        int co = i & 31, ci = i >> 5;
        wb[OFF_C4 + i] = ew4[co * 64 + ci];
    } else if (b < 352) {                // dec1: KK=9 CIN=32 COUT=64 (18432)
        int i = (b - 280) * 256 + t;
        int co = i & 63, r = i >> 6, ci = r & 31, tap = r >> 5;
        wb[OFF_D1 + i] = dw1[(co * 32 + ci) * 9 + tap];
    } else if (b < 480) {                // deconv1: 4 cls x 4 taps CIN=64 COUT=32 (32768)
        int i = (b - 352) * 256 + t;
        int co = i & 31, r = i >> 5, ci = r & 63, jt = r >> 6;
        int cls = jt >> 2, j = jt & 3;
        int py = cls >> 1, px = cls & 1;
        int ty = j >> 1, tx = j & 1;
        int ky = ty ? 3 - py : 1 - py;
        int kx = tx ? 3 - px : 1 - px;
        wb[OFF_T1 + i] = tw1[(ci * 32 + co) * 16 + ky * 4 + kx];
    } else {                             // codebook norms (512)
        int k = (b - 480) * 256 + t;
        if (k < 512) {
            float s = 0.f;
            const float* c = cb + k * 32;
            #pragma unroll
            for (int d = 0; d < 32; d++) s = fmaf(c[d], c[d], s);
            cn[k] = s;
        }
    }
}

// ------------------- tf32 implicit-GEMM conv, M-tile 256, double-buffered -------------------
// Logical output grid 32x32 per image; 256 m per block, 8 warps x 2 m16 tiles.
// X3: 3xTF32 hi/lo split (encoder path). DECONV: 4 parity classes via blockIdx.y,
// output written strided (OS=2) into W-wide map.
template<int CIN, int HIN, int COUT, int S, int KW, int NTAPS, int P,
         bool DECONV, int OS, int W, bool X3, bool RELU>
__global__ void k_igemm(const float* __restrict__ in, const float* __restrict__ wb,
                        const float* __restrict__ bias, float* __restrict__ out) {
    constexpr int NS = X3 ? 2 : 1;
    constexpr int CI8 = CIN / 8;
    constexpr int NC = NTAPS * CI8;
    constexpr int NT = COUT / 8;
    __shared__ unsigned As[2][NS][8][264];
    __shared__ unsigned Bs[2][NS][8][COUT + 8];

    const int t = threadIdx.x, lane = t & 31, wrp = t >> 5;
    const int g = lane >> 2, tg = lane & 3;
    const int n = blockIdx.z;
    const int m0 = blockIdx.x * 256;

    int py = 0, px = 0;
    const float* wbp = wb;
    if (DECONV) { int cls = blockIdx.y; py = cls >> 1; px = cls & 1; wbp += cls * NTAPS * CIN * COUT; }

    int oyS[8], oxS[8];
    #pragma unroll
    for (int j = 0; j < 8; j++) {
        int p = m0 + j * 32 + lane;
        oyS[j] = (p >> 5) * S;
        oxS[j] = (p & 31) * S;
    }

    float acc[NT][2][4];
    #pragma unroll
    for (int i = 0; i < NT; i++)
        #pragma unroll
        for (int mt = 0; mt < 2; mt++)
            #pragma unroll
            for (int j = 0; j < 4; j++) acc[i][mt][j] = 0.f;

    auto stage = [&](int chunk, int buf) {
        const int tap = chunk / CI8;
        const int ci0 = (chunk % CI8) * 8;
        int dy, dx;
        if (DECONV) { dy = py - (tap >> 1); dx = px - (tap & 1); }
        else        { dy = tap / KW - P;    dx = tap % KW - P; }
        const float* base = in + ((long)n * CIN + ci0 + wrp) * (HIN * HIN);
        #pragma unroll
        for (int j = 0; j < 8; j++) {
            int iy = oyS[j] + dy, ix = oxS[j] + dx;
            float v = ((unsigned)iy < (unsigned)HIN && (unsigned)ix < (unsigned)HIN)
                      ? base[iy * HIN + ix] : 0.f;
            unsigned hi = f2tf32(v);
            As[buf][0][wrp][j * 32 + lane] = hi;
            if (X3) As[buf][1][wrp][j * 32 + lane] = f2tf32(v - __uint_as_float(hi));
        }
        #pragma unroll
        for (int i2 = 0; i2 < (8 * COUT + 255) / 256; i2++) {
            int i = t + i2 * 256;
            if ((8 * COUT % 256 == 0) || i < 8 * COUT) {
                int bk = i / COUT, co = i % COUT;
                float v = wbp[(tap * CIN + ci0 + bk) * COUT + co];
                unsigned hi = f2tf32(v);
                Bs[buf][0][bk][co] = hi;
                if (X3) Bs[buf][1][bk][co] = f2tf32(v - __uint_as_float(hi));
            }
        }
    };

    stage(0, 0);
    __syncthreads();
    for (int c = 0; c < NC; c++) {
        const int b = c & 1;
        if (c + 1 < NC) stage(c + 1, b ^ 1);

        unsigned ah[2][4], al[2][4];
        #pragma unroll
        for (int mt = 0; mt < 2; mt++) {
            int mb = wrp * 32 + mt * 16;
            ah[mt][0] = As[b][0][tg][mb + g];     ah[mt][1] = As[b][0][tg][mb + g + 8];
            ah[mt][2] = As[b][0][tg + 4][mb + g]; ah[mt][3] = As[b][0][tg + 4][mb + g + 8];
            if (X3) {
                al[mt][0] = As[b][NS-1][tg][mb + g];     al[mt][1] = As[b][NS-1][tg][mb + g + 8];
                al[mt][2] = As[b][NS-1][tg + 4][mb + g]; al[mt][3] = As[b][NS-1][tg + 4][mb + g + 8];
            }
        }
        #pragma unroll
        for (int nt = 0; nt < NT; nt++) {
            unsigned bh0 = Bs[b][0][tg][nt * 8 + g], bh1 = Bs[b][0][tg + 4][nt * 8 + g];
            unsigned bl0 = 0, bl1 = 0;
            if (X3) { bl0 = Bs[b][NS-1][tg][nt * 8 + g]; bl1 = Bs[b][NS-1][tg + 4][nt * 8 + g]; }
            #pragma unroll
            for (int mt = 0; mt < 2; mt++) {
                if (X3) {
                    mma_tf32(acc[nt][mt][0], acc[nt][mt][1], acc[nt][mt][2], acc[nt][mt][3],
                             al[mt][0], al[mt][1], al[mt][2], al[mt][3], bh0, bh1);
                    mma_tf32(acc[nt][mt][0], acc[nt][mt][1], acc[nt][mt][2], acc[nt][mt][3],
                             ah[mt][0], ah[mt][1], ah[mt][2], ah[mt][3], bl0, bl1);
                }
                mma_tf32(acc[nt][mt][0], acc[nt][mt][1], acc[nt][mt][2], acc[nt][mt][3],
                         ah[mt][0], ah[mt][1], ah[mt][2], ah[mt][3], bh0, bh1);
            }
        }
        __syncthreads();
    }

    // epilogue: direct strided stores
    int eoy[4], eox[4];
    {
        int rowm[4] = {wrp * 32 + g, wrp * 32 + g + 8, wrp * 32 + 16 + g, wrp * 32 + 16 + g + 8};
        #pragma unroll
        for (int h = 0; h < 4; h++) {
            int p = m0 + rowm[h];
            eoy[h] = (p >> 5) * OS + py;
            eox[h] = (p & 31) * OS + px;
        }
    }
    #pragma unroll
    for (int nt = 0; nt < NT; nt++) {
        int co = nt * 8 + 2 * tg;
        float b0 = __ldg(bias + co), b1 = __ldg(bias + co + 1);
        #pragma unroll
        for (int mt = 0; mt < 2; mt++) {
            #pragma unroll
            for (int hh = 0; hh < 2; hh++) {
                int h = mt * 2 + hh;
                float v0 = acc[nt][mt][hh * 2 + 0] + b0;
                float v1 = acc[nt][mt][hh * 2 + 1] + b1;
                if (RELU) { v0 = fmaxf(v0, 0.f); v1 = fmaxf(v1, 0.f); }
                long ob = (((long)n * COUT + co) * W + eoy[h]) * W + eox[h];
                out[ob] = v0;
                out[ob + (long)W * W] = v1;
            }
        }
    }
}

// ------------------- conv1 (scalar; tiny K, memory-ish) -------------------
template<int CIN, int HIN, int K, int S, int P, int COUT, int CT, int ST, bool RELU>
__global__ void k_convt(const float* __restrict__ in, const float* __restrict__ w,
                        const float* __restrict__ bias, float* __restrict__ out) {
    constexpr int HOUT = (HIN + 2 * P - K) / S + 1;
    constexpr int KK = K * K;
    __shared__ float sw[CT * CIN * KK];
    const int co0 = blockIdx.y * CT;
    const int n   = blockIdx.z;
    const int t   = threadIdx.x;
    for (int i = t; i < CT * CIN * KK; i += 256) {
        int c = i / (CIN * KK), rest = i % (CIN * KK);
        sw[i] = w[(co0 + c) * CIN * KK + rest];
    }
    __syncthreads();

    const int p0  = (blockIdx.x * 256 + t) * ST;
    const int oy  = p0 / HOUT;
    const int ox0 = p0 % HOUT;

    float acc[CT][ST];
    #pragma unroll
    for (int c = 0; c < CT; c++) {
        float bv = bias[co0 + c];
        #pragma unroll
        for (int s = 0; s < ST; s++) acc[c][s] = bv;
    }

    const float* ib = in + (long)n * CIN * HIN * HIN;
    for (int ci = 0; ci < CIN; ci++) {
        const float* ic = ib + ci * HIN * HIN;
        #pragma unroll
        for (int ky = 0; ky < K; ky++) {
            int iy = oy * S - P + ky;
            if ((unsigned)iy < (unsigned)HIN) {
                const float* row = ic + iy * HIN;
                #pragma unroll
                for (int kx = 0; kx < K; kx++) {
                    float xv[ST];
                    #pragma unroll
                    for (int s = 0; s < ST; s++) {
                        int ix = (ox0 + s) * S - P + kx;
                        xv[s] = ((unsigned)ix < (unsigned)HIN) ? row[ix] : 0.f;
                    }
                    #pragma unroll
                    for (int c = 0; c < CT; c++) {
                        float wv = sw[(c * CIN + ci) * KK + ky * K + kx];
                        #pragma unroll
                        for (int s = 0; s < ST; s++)
                            acc[c][s] = fmaf(xv[s], wv, acc[c][s]);
                    }
                }
            }
        }
    }

    #pragma unroll
    for (int c = 0; c < CT; c++) {
        float* op = out + (((long)n * COUT + co0 + c) * HOUT + oy) * HOUT + ox0;
        #pragma unroll
        for (int s = 0; s < ST; s++)
            op[s] = RELU ? fmaxf(acc[c][s], 0.f) : acc[c][s];
    }
}

// ------------------- deconv2: [256,32,64,64] -> [256,1,128,128], sigmoid -------------------
__global__ void k_deconv2(const float* __restrict__ in, const float* __restrict__ w,
                          const float* __restrict__ bias, float* __restrict__ out) {
    __shared__ float sw[512];
    const int t = threadIdx.x;
    const int n = blockIdx.z;
    for (int i = t; i < 512; i += 256) sw[i] = w[i];
    __syncthreads();

    const int ti = blockIdx.x * 256 + t;      // 0..511
    const int ty = ti >> 4, tx = ti & 15;
    const float bv = __ldg(bias);

    float acc[4][8];
    #pragma unroll
    for (int r = 0; r < 4; r++)
        #pragma unroll
        for (int c = 0; c < 8; c++) acc[r][c] = 0.f;

    const float* ib = in + (long)n * 32 * 4096;
    for (int ci = 0; ci < 32; ci++) {
        const float* ic = ib + ci * 4096;
        float xv[4][6];
        #pragma unroll
        for (int rr = 0; rr < 4; rr++) {
            int iy = 2 * ty - 1 + rr;
            bool vy = (unsigned)iy < 64u;
            const float* row = ic + iy * 64;
            int c0 = 4 * tx - 1;
            xv[rr][0] = (vy && c0 >= 0) ? row[c0] : 0.f;
            if (vy) {
                float4 m4 = *(const float4*)(row + 4 * tx);
                xv[rr][1] = m4.x; xv[rr][2] = m4.y; xv[rr][3] = m4.z; xv[rr][4] = m4.w;
            } else {
                xv[rr][1] = xv[rr][2] = xv[rr][3] = xv[rr][4] = 0.f;
            }
            int c5 = 4 * tx + 4;
            xv[rr][5] = (vy && c5 < 64) ? row[c5] : 0.f;
        }
        float wr[16];
        #pragma unroll
        for (int k = 0; k < 16; k++) wr[k] = sw[ci * 16 + k];
        #pragma unroll
        for (int r = 0; r < 4; r++) {
            const int pyy = r & 1;
            const int rowA = (r >> 1) + pyy + 1, rowB = rowA - 1;
            #pragma unroll
            for (int c = 0; c < 8; c++) {
                const int pxx = c & 1;
                const int colA = (c >> 1) + pxx + 1, colB = colA - 1;
                float a = acc[r][c];
                a = fmaf(xv[rowA][colA], wr[(1 - pyy) * 4 + (1 - pxx)], a);
                a = fmaf(xv[rowA][colB], wr[(1 - pyy) * 4 + (3 - pxx)], a);
                a = fmaf(xv[rowB][colA], wr[(3 - pyy) * 4 + (1 - pxx)], a);
                a = fmaf(xv[rowB][colB], wr[(3 - pyy) * 4 + (3 - pxx)], a);
                acc[r][c] = a;
            }
        }
    }

    float* ob = out + (long)n * 16384;
    #pragma unroll
    for (int r = 0; r < 4; r++) {
        int oy = 4 * ty + r;
        float v[8];
        #pragma unroll
        for (int c = 0; c < 8; c++)
            v[c] = 1.f / (1.f + expf(-(acc[r][c] + bv)));
        *(float4*)(ob + oy * 128 + 8 * tx)     = make_float4(v[0], v[1], v[2], v[3]);
        *(float4*)(ob + oy * 128 + 8 * tx + 4) = make_float4(v[4], v[5], v[6], v[7]);
    }
}

// ------------------- vector quantization on tensor cores (3xTF32) -------------------
// Block: 128 positions, 256 threads. dists = ||c||^2 - 2 z.c, K processed in
// 16 chunks of 32 codewords; per-fragment running argmin, ascending-k scan with
// strict < (+ index tie-break across lanes) preserves first-min semantics.
__global__ void k_vq_tc(const float* __restrict__ z, const float* __restrict__ cb,
                        const float* __restrict__ cn, float* __restrict__ q,
                        float* __restrict__ lpart) {
    __shared__ unsigned As[2][32][136];   // z tile hi/lo [d][m]
    __shared__ unsigned Bs[2][32][40];    // codebook chunk hi/lo [d][k]
    __shared__ float scn[32];
    __shared__ int sidx[128];
    __shared__ float red[256];
    const int t = threadIdx.x, lane = t & 31, wrp = t >> 5;
    const int g = lane >> 2, tg = lane & 3;
    const int n  = blockIdx.x >> 3;
    const int p0 = (blockIdx.x & 7) * 128;
    const int mw = wrp * 16;

    for (int i = t; i < 4096; i += 256) {
        int d = i >> 7, m = i & 127;
        float v = z[((long)n * 32 + d) * 1024 + p0 + m];
        unsigned hi = f2tf32(v);
        As[0][d][m] = hi;
        As[1][d][m] = f2tf32(v - __uint_as_float(hi));
    }
    __syncthreads();

    unsigned ah[4][4], al[4][4];
    #pragma unroll
    for (int s = 0; s < 4; s++) {
        ah[s][0] = As[0][s * 8 + tg][mw + g];     ah[s][1] = As[0][s * 8 + tg][mw + g + 8];
        ah[s][2] = As[0][s * 8 + tg + 4][mw + g]; ah[s][3] = As[0][s * 8 + tg + 4][mw + g + 8];
        al[s][0] = As[1][s * 8 + tg][mw + g];     al[s][1] = As[1][s * 8 + tg][mw + g + 8];
        al[s][2] = As[1][s * 8 + tg + 4][mw + g]; al[s][3] = As[1][s * 8 + tg + 4][mw + g + 8];
    }

    float best0 = 3.4e38f, best1 = 3.4e38f;
    int bidx0 = 0, bidx1 = 0;

    for (int ch = 0; ch < 16; ch++) {
        const int k0 = ch * 32;
        __syncthreads();
        for (int i = t; i < 1024; i += 256) {
            int d = i & 31, kk = i >> 5;
            float v = cb[(k0 + kk) * 32 + d];
            unsigned hi = f2tf32(v);
            Bs[0][d][kk] = hi;
            Bs[1][d][kk] = f2tf32(v - __uint_as_float(hi));
        }
        if (t < 32) scn[t] = cn[k0 + t];
        __syncthreads();

        #pragma unroll
        for (int nt = 0; nt < 4; nt++) {
            float a0 = 0.f, a1 = 0.f, a2 = 0.f, a3 = 0.f;
            #pragma unroll
            for (int s = 0; s < 4; s++) {
                unsigned bh0 = Bs[0][s * 8 + tg][nt * 8 + g], bh1 = Bs[0][s * 8 + tg + 4][nt * 8 + g];
                unsigned bl0 = Bs[1][s * 8 + tg][nt * 8 + g], bl1 = Bs[1][s * 8 + tg + 4][nt * 8 + g];
                mma_tf32(a0, a1, a2, a3, al[s][0], al[s][1], al[s][2], al[s][3], bh0, bh1);
                mma_tf32(a0, a1, a2, a3, ah[s][0], ah[s][1], ah[s][2], ah[s][3], bl0, bl1);
                mma_tf32(a0, a1, a2, a3, ah[s][0], ah[s][1], ah[s][2], ah[s][3], bh0, bh1);
            }
            int kc0 = k0 + nt * 8 + 2 * tg, kc1 = kc0 + 1;
            float c0 = scn[nt * 8 + 2 * tg], c1 = scn[nt * 8 + 2 * tg + 1];
            float d00 = fmaf(-2.f, a0, c0), d01 = fmaf(-2.f, a1, c1);
            float d10 = fmaf(-2.f, a2, c0), d11 = fmaf(-2.f, a3, c1);
            if (d00 < best0) { best0 = d00; bidx0 = kc0; }
            if (d01 < best0) { best0 = d01; bidx0 = kc1; }
            if (d10 < best1) { best1 = d10; bidx1 = kc0; }
            if (d11 < best1) { best1 = d11; bidx1 = kc1; }
        }
    }

    #pragma unroll
    for (int off = 1; off < 4; off <<= 1) {
        float ob; int oi;
        ob = __shfl_down_sync(0xffffffffu, best0, off, 4);
        oi = __shfl_down_sync(0xffffffffu, bidx0, off, 4);
        if (ob < best0 || (ob == best0 && oi < bidx0)) { best0 = ob; bidx0 = oi; }
        ob = __shfl_down_sync(0xffffffffu, best1, off, 4);
        oi = __shfl_down_sync(0xffffffffu, bidx1, off, 4);
        if (ob < best1 || (ob == best1 && oi < bidx1)) { best1 = ob; bidx1 = oi; }
    }
    if (tg == 0) { sidx[mw + g] = bidx0; sidx[mw + g + 8] = bidx1; }
    __syncthreads();

    float lsum = 0.f;
    for (int i = t; i < 4096; i += 256) {
        int d = i >> 7, m = i & 127;
        long zi = ((long)n * 32 + d) * 1024 + p0 + m;
        float qv = __ldg(cb + sidx[m] * 32 + d);
        float zv = z[zi];
        q[zi] = qv;
        float e = qv - zv;
        lsum = fmaf(e, e, lsum);
    }
    red[t] = lsum;
    __syncthreads();
    for (int s = 128; s > 0; s >>= 1) {
        if (t < s) red[t] += red[t + s];
        __syncthreads();
    }
    if (t == 0) lpart[blockIdx.x] = red[0];
}

// deterministic fixed-order final reduction: vq_loss = 1.26 * mean
__global__ void k_loss(const float* __restrict__ lpart, float* __restrict__ out,
                       int out_size) {
    __shared__ float red[256];
    const int t = threadIdx.x;
    float s = 0.f;
    #pragma unroll
    for (int j = 0; j < 8; j++) s += lpart[t + 256 * j];
    red[t] = s;
    __syncthreads();
    for (int st = 128; st > 0; st >>= 1) {
        if (t < st) red[t] += red[t + st];
        __syncthreads();
    }
    if (t == 0) out[out_size - 1] = 1.26f * red[0] / 8388608.0f;
}

// ------------------- launch -------------------
extern "C" void kernel_launch(void* const* d_in, const int* in_sizes, int n_in,
                              void* d_out, int out_size) {
    const float* x   = (const float*)d_in[0];
    const float* ew1 = (const float*)d_in[1];  const float* eb1 = (const float*)d_in[2];
    const float* ew2 = (const float*)d_in[3];  const float* eb2 = (const float*)d_in[4];
    const float* ew3 = (const float*)d_in[5];  const float* eb3 = (const float*)d_in[6];
    const float* ew4 = (const float*)d_in[7];  const float* eb4 = (const float*)d_in[8];
    const float* cb  = (const float*)d_in[9];
    const float* dw1 = (const float*)d_in[10]; const float* db1 = (const float*)d_in[11];
    const float* tw1 = (const float*)d_in[12]; const float* tb1 = (const float*)d_in[13];
    const float* tw2 = (const float*)d_in[14]; const float* tb2 = (const float*)d_in[15];
    float* out = (float*)d_out;

    float *pa, *pb, *pc, *pz, *pq, *pl, *pwb, *pcn;
    cudaGetSymbolAddress((void**)&pa, g_a);
    cudaGetSymbolAddress((void**)&pb, g_b);
    cudaGetSymbolAddress((void**)&pc, g_c);
    cudaGetSymbolAddress((void**)&pz, g_z);
    cudaGetSymbolAddress((void**)&pq, g_q);
    cudaGetSymbolAddress((void**)&pl, g_lpart);
    cudaGetSymbolAddress((void**)&pwb, g_wb);
    cudaGetSymbolAddress((void**)&pcn, g_cn);

    // fused weight prep + codebook norms
    k_prep_all<<<482, 256>>>(ew2, ew3, ew4, dw1, tw1, cb, pwb, pcn);

    // Encoder
    k_convt<1, 128, 4, 2, 1, 32, 8, 4, true><<<dim3(4, 4, BATCH), 256>>>(x, ew1, eb1, pa);
    k_igemm<32, 64, 64, 2, 4, 16, 1, false, 1, 32, true, true>
        <<<dim3(4, 1, BATCH), 256>>>(pa, pwb + OFF_C2, eb2, pb);          // conv2
    k_igemm<64, 32, 64, 1, 3, 9, 1, false, 1, 32, true, true>
        <<<dim3(4, 1, BATCH), 256>>>(pb, pwb + OFF_C3, eb3, pc);          // conv3
    k_igemm<64, 32, 32, 1, 1, 1, 0, false, 1, 32, true, false>
        <<<dim3(4, 1, BATCH), 256>>>(pc, pwb + OFF_C4, eb4, pz);          // conv4

    // Vector quantization (tensor cores, 3xTF32)
    k_vq_tc<<<2048, 256>>>(pz, cb, pcn, pq, pl);

    // Decoder
    k_igemm<32, 32, 64, 1, 3, 9, 1, false, 1, 32, false, true>
        <<<dim3(4, 1, BATCH), 256>>>(pq, pwb + OFF_D1, db1, pc);          // dec1
    k_igemm<64, 32, 32, 1, 1, 4, 0, true, 2, 64, false, true>
        <<<dim3(4, 4, BATCH), 256>>>(pc, pwb + OFF_T1, tb1, pa);          // deconv1
    k_deconv2<<<dim3(2, 1, BATCH), 256>>>(pa, tw2, tb2, out);             // deconv2

    // loss
    k_loss<<<1, 256>>>(pl, out, out_size);
}